// round 1
// baseline (speedup 1.0000x reference)
#include <cuda_runtime.h>
#include <math.h>

#define B_SZ  4
#define S_LEN 2048
#define D_DIM 1024
#define M_ROWS (B_SZ * S_LEN)   // 8192

// ---------------- scratch (allocation-free: __device__ globals) ----------------
__device__ float g_Q[(size_t)M_ROWS * D_DIM];                 // 32 MB
__device__ float g_K[(size_t)M_ROWS * D_DIM];                 // 32 MB
__device__ float g_V[(size_t)M_ROWS * D_DIM];                 // 32 MB
__device__ float g_S[(size_t)B_SZ * S_LEN * S_LEN];           // 64 MB

// ---------------- generic tiled fp32 GEMM ----------------
// C[M,N] = alpha * A[M,K] @ B(') + bias
//   TB=true : B given as [N,K] row-major (C = A @ B^T)  -- used for x@W^T and Q@K^T
//   TB=false: B given as [K,N] row-major (C = A @ B)    -- used for P@V
// blockIdx.z batches with strides sA/sB/sC.
// Requires M%128==0, N%128==0, K%16==0 (true for all calls here).
template <bool TB>
__global__ void __launch_bounds__(256) gemm_kernel(
    const float* __restrict__ A, const float* __restrict__ B,
    const float* __restrict__ bias, float* __restrict__ C,
    int M, int N, int K,
    long long sA, long long sB, long long sC, float alpha)
{
    A += (long long)blockIdx.z * sA;
    B += (long long)blockIdx.z * sB;
    C += (long long)blockIdx.z * sC;

    __shared__ float As[16][132];
    __shared__ float Bs[16][132];

    const int tid = threadIdx.x;
    const int bm  = blockIdx.y * 128;
    const int bn  = blockIdx.x * 128;
    const int tx  = tid & 15;         // 0..15  -> 8 output cols each
    const int ty  = tid >> 4;         // 0..15  -> 8 output rows each

    // load mappings
    const int lrow = tid >> 2;        // 0..63  (row within tile, +64 second pass)
    const int lcol = (tid & 3) << 2;  // 0,4,8,12 (k offset, float4)
    const int nrow = tid >> 5;        // 0..7   (k row for NN B load)
    const int ncol = (tid & 31) << 2; // 0..124 (n offset, float4)

    float acc[8][8];
    #pragma unroll
    for (int i = 0; i < 8; i++)
        #pragma unroll
        for (int j = 0; j < 8; j++) acc[i][j] = 0.0f;

    for (int k0 = 0; k0 < K; k0 += 16) {
        // A tile: rows [bm, bm+128), k cols [k0, k0+16) -> transposed into As[k][m]
        #pragma unroll
        for (int r = 0; r < 2; r++) {
            float4 va = *(const float4*)(A + (long long)(bm + lrow + r * 64) * K + (k0 + lcol));
            As[lcol + 0][lrow + r * 64] = va.x;
            As[lcol + 1][lrow + r * 64] = va.y;
            As[lcol + 2][lrow + r * 64] = va.z;
            As[lcol + 3][lrow + r * 64] = va.w;
        }
        if (TB) {
            // B is [N,K]: rows [bn, bn+128), k cols [k0,k0+16) -> Bs[k][n]
            #pragma unroll
            for (int r = 0; r < 2; r++) {
                float4 vb = *(const float4*)(B + (long long)(bn + lrow + r * 64) * K + (k0 + lcol));
                Bs[lcol + 0][lrow + r * 64] = vb.x;
                Bs[lcol + 1][lrow + r * 64] = vb.y;
                Bs[lcol + 2][lrow + r * 64] = vb.z;
                Bs[lcol + 3][lrow + r * 64] = vb.w;
            }
        } else {
            // B is [K,N]: k rows [k0,k0+16), cols [bn, bn+128) -> Bs[k][n] direct
            #pragma unroll
            for (int r = 0; r < 2; r++) {
                float4 vb = *(const float4*)(B + (long long)(k0 + nrow + r * 8) * N + (bn + ncol));
                *(float4*)&Bs[nrow + r * 8][ncol] = vb;
            }
        }
        __syncthreads();

        #pragma unroll
        for (int k = 0; k < 16; k++) {
            float ra[8], rb[8];
            #pragma unroll
            for (int i = 0; i < 8; i++) ra[i] = As[k][ty * 8 + i];
            #pragma unroll
            for (int j = 0; j < 8; j++) rb[j] = Bs[k][tx * 8 + j];
            #pragma unroll
            for (int i = 0; i < 8; i++)
                #pragma unroll
                for (int j = 0; j < 8; j++)
                    acc[i][j] = fmaf(ra[i], rb[j], acc[i][j]);
        }
        __syncthreads();
    }

    // epilogue: alpha scale + optional bias, vectorized store
    #pragma unroll
    for (int i = 0; i < 8; i++) {
        float* crow = C + (long long)(bm + ty * 8 + i) * N + (bn + tx * 8);
        #pragma unroll
        for (int j = 0; j < 8; j += 4) {
            float4 o;
            o.x = acc[i][j + 0] * alpha;
            o.y = acc[i][j + 1] * alpha;
            o.z = acc[i][j + 2] * alpha;
            o.w = acc[i][j + 3] * alpha;
            if (bias != nullptr) {
                o.x += bias[bn + tx * 8 + j + 0];
                o.y += bias[bn + tx * 8 + j + 1];
                o.z += bias[bn + tx * 8 + j + 2];
                o.w += bias[bn + tx * 8 + j + 3];
            }
            *(float4*)(crow + j) = o;
        }
    }
}

// ---------------- RoPE on Q and K in place ----------------
// grid covers M_ROWS * (D/2) pairs; matches reference:
//   inv_freq[i] = 10000^(-(2i)/D), ang = s * inv_freq[i]
__global__ void __launch_bounds__(256) rope_kernel(float* __restrict__ Q, float* __restrict__ K)
{
    int idx = blockIdx.x * 256 + threadIdx.x;    // 0 .. M_ROWS*512-1
    int i   = idx & 511;                         // pair index
    int row = idx >> 9;                          // b*S + s
    int s   = row & (S_LEN - 1);

    float inv_freq = powf(10000.0f, -(float)(2 * i) * (1.0f / (float)D_DIM));
    float ang = (float)s * inv_freq;
    float sn, cs;
    sincosf(ang, &sn, &cs);

    long long off = (long long)row * D_DIM + 2 * i;
    float q0 = Q[off], q1 = Q[off + 1];
    Q[off]     = q0 * cs - q1 * sn;
    Q[off + 1] = q0 * sn + q1 * cs;
    float k0 = K[off], k1 = K[off + 1];
    K[off]     = k0 * cs - k1 * sn;
    K[off + 1] = k0 * sn + k1 * cs;
}

// ---------------- row softmax over S_LEN, in place ----------------
__global__ void __launch_bounds__(256) softmax_kernel(float* __restrict__ P)
{
    float* row = P + (long long)blockIdx.x * S_LEN;
    const int tid = threadIdx.x;
    __shared__ float red[8];

    float v[8];
    float m = -1e30f;
    #pragma unroll
    for (int i = 0; i < 8; i++) {
        v[i] = row[tid + i * 256];
        m = fmaxf(m, v[i]);
    }
    // block max
    #pragma unroll
    for (int o = 16; o > 0; o >>= 1) m = fmaxf(m, __shfl_xor_sync(0xFFFFFFFFu, m, o));
    if ((tid & 31) == 0) red[tid >> 5] = m;
    __syncthreads();
    m = red[0];
    #pragma unroll
    for (int i = 1; i < 8; i++) m = fmaxf(m, red[i]);
    __syncthreads();

    float sum = 0.0f;
    #pragma unroll
    for (int i = 0; i < 8; i++) {
        v[i] = expf(v[i] - m);
        sum += v[i];
    }
    // block sum
    #pragma unroll
    for (int o = 16; o > 0; o >>= 1) sum += __shfl_xor_sync(0xFFFFFFFFu, sum, o);
    if ((tid & 31) == 0) red[tid >> 5] = sum;
    __syncthreads();
    sum = 0.0f;
    #pragma unroll
    for (int i = 0; i < 8; i++) sum += red[i];

    float inv = 1.0f / sum;
    #pragma unroll
    for (int i = 0; i < 8; i++) row[tid + i * 256] = v[i] * inv;
}

// ---------------- launch ----------------
extern "C" void kernel_launch(void* const* d_in, const int* in_sizes, int n_in,
                              void* d_out, int out_size)
{
    const float* x  = (const float*)d_in[0];
    const float* wq = (const float*)d_in[1];
    const float* bq = (const float*)d_in[2];
    const float* wk = (const float*)d_in[3];
    const float* bk = (const float*)d_in[4];
    const float* wv = (const float*)d_in[5];
    const float* bv = (const float*)d_in[6];
    float* out = (float*)d_out;

    float *Q, *K, *V, *Sc;
    cudaGetSymbolAddress((void**)&Q,  g_Q);
    cudaGetSymbolAddress((void**)&K,  g_K);
    cudaGetSymbolAddress((void**)&V,  g_V);
    cudaGetSymbolAddress((void**)&Sc, g_S);

    dim3 blk(256);

    // 1) QKV projections: [8192,1024] = x @ W^T + b
    dim3 gQKV(D_DIM / 128, M_ROWS / 128, 1);
    gemm_kernel<true><<<gQKV, blk>>>(x, wq, bq, Q, M_ROWS, D_DIM, D_DIM, 0, 0, 0, 1.0f);
    gemm_kernel<true><<<gQKV, blk>>>(x, wk, bk, K, M_ROWS, D_DIM, D_DIM, 0, 0, 0, 1.0f);
    gemm_kernel<true><<<gQKV, blk>>>(x, wv, bv, V, M_ROWS, D_DIM, D_DIM, 0, 0, 0, 1.0f);

    // 2) RoPE on Q, K
    rope_kernel<<<(M_ROWS * (D_DIM / 2)) / 256, blk>>>(Q, K);

    // 3) scores = Q @ K^T / sqrt(D), batched over B
    dim3 gS(S_LEN / 128, S_LEN / 128, B_SZ);
    gemm_kernel<true><<<gS, blk>>>(Q, K, nullptr, Sc, S_LEN, S_LEN, D_DIM,
                                   (long long)S_LEN * D_DIM, (long long)S_LEN * D_DIM,
                                   (long long)S_LEN * S_LEN, 0.03125f);

    // 4) softmax over rows
    softmax_kernel<<<M_ROWS, blk>>>(Sc);

    // 5) out = P @ V, batched over B
    dim3 gO(D_DIM / 128, S_LEN / 128, B_SZ);
    gemm_kernel<false><<<gO, blk>>>(Sc, V, nullptr, out, S_LEN, D_DIM, S_LEN,
                                    (long long)S_LEN * S_LEN, (long long)S_LEN * D_DIM,
                                    (long long)S_LEN * D_DIM, 1.0f);
}

// round 3
// speedup vs baseline: 4.1701x; 4.1701x over previous
#include <cuda_runtime.h>
#include <cuda_bf16.h>
#include <math.h>
#include <stdint.h>

#define B_SZ  4
#define S_LEN 2048
#define D_DIM 1024
#define M_ROWS (B_SZ * S_LEN)   // 8192

// ---------------- scratch (allocation-free: __device__ globals) ----------------
__device__ uint32_t g_Xs[(size_t)M_ROWS * D_DIM];              // 32 MB  split(x)
__device__ uint32_t g_Ws[(size_t)3 * D_DIM * D_DIM];           // 12 MB  split(wq|wk|wv)
__device__ float    g_Q [(size_t)M_ROWS * D_DIM];              // 32 MB  fp32 then split in place
__device__ float    g_K [(size_t)M_ROWS * D_DIM];              // 32 MB
__device__ float    g_V [(size_t)M_ROWS * D_DIM];              // 32 MB
__device__ uint32_t g_Vt[(size_t)M_ROWS * D_DIM];              // 32 MB  split(V^T)
__device__ float    g_S [(size_t)B_SZ * S_LEN * S_LEN];        // 64 MB  fp32 then split in place

// ======================= helpers =======================
__device__ __forceinline__ uint32_t smem_u32(const void* p) {
    uint32_t a;
    asm("{ .reg .u64 t; cvta.to.shared.u64 t, %1; cvt.u32.u64 %0, t; }" : "=r"(a) : "l"(p));
    return a;
}
// fp32 -> packed (hi bf16 in low 16, lo bf16 in high 16)
__device__ __forceinline__ uint32_t split_pack(float f) {
    __nv_bfloat16 h = __float2bfloat16(f);
    float hf = __bfloat162float(h);
    __nv_bfloat16 l = __float2bfloat16(f - hf);
    return (uint32_t)__bfloat16_as_ushort(h) | ((uint32_t)__bfloat16_as_ushort(l) << 16);
}
__device__ __forceinline__ void lds2(uint32_t addr, uint32_t& x, uint32_t& y) {
    asm volatile("ld.shared.v2.b32 {%0,%1}, [%2];" : "=r"(x), "=r"(y) : "r"(addr));
}
__device__ __forceinline__ void mma16816(float& d0, float& d1, float& d2, float& d3,
                                         uint32_t a0, uint32_t a1, uint32_t a2, uint32_t a3,
                                         uint32_t b0, uint32_t b1) {
    asm volatile(
        "mma.sync.aligned.m16n8k16.row.col.f32.bf16.bf16.f32 "
        "{%0,%1,%2,%3},{%4,%5,%6,%7},{%8,%9},{%0,%1,%2,%3};"
        : "+f"(d0), "+f"(d1), "+f"(d2), "+f"(d3)
        : "r"(a0), "r"(a1), "r"(a2), "r"(a3), "r"(b0), "r"(b1));
}
__device__ __forceinline__ void cp16(uint32_t dst, const void* src) {
    asm volatile("cp.async.cg.shared.global [%0], [%1], 16;"
                 :: "r"(dst), "l"(__cvta_generic_to_global(src)) : "memory");
}
#define CP_COMMIT() asm volatile("cp.async.commit_group;" ::: "memory")
#define CP_WAIT2()  asm volatile("cp.async.wait_group 2;" ::: "memory")

// swizzled smem byte offset within a [rows][32 u32] tile (128B rows, 16B atom XOR)
__device__ __forceinline__ uint32_t swo(int row, int byteCol) {
    return (uint32_t)(row * 128 + (((byteCol >> 4) ^ (row & 7)) << 4) + (byteCol & 15));
}

// ======================= split-bf16 NT GEMM (3 MMAs per product) =======================
// C[M,N] = alpha * decode(A) @ decode(B)^T + bias
//   A: u32-split [M,K] row-major; B: u32-split [N,K] row-major; C fp32.
// CTA tile 128x128, BK=32 (u32 k-elems), 3-stage cp.async pipeline, 256 threads.
#define STAGE_BYTES 16384                     // one matrix tile: 128*32*4
#define SMEM_GEMM_BYTES (3 * 2 * STAGE_BYTES) // 98304

__device__ __forceinline__ void issue_stage(uint32_t abase, uint32_t bbase,
                                            const uint32_t* Ag, const uint32_t* Bg,
                                            int K, int tid) {
    #pragma unroll
    for (int i = 0; i < 4; i++) {
        int cidx = tid + i * 256;
        int row = cidx >> 3, c16 = cidx & 7;
        cp16(abase + row * 128 + (((c16 ^ (row & 7))) << 4), Ag + (long long)row * K + c16 * 4);
    }
    #pragma unroll
    for (int i = 0; i < 4; i++) {
        int cidx = tid + i * 256;
        int row = cidx >> 3, c16 = cidx & 7;
        cp16(bbase + row * 128 + (((c16 ^ (row & 7))) << 4), Bg + (long long)row * K + c16 * 4);
    }
    CP_COMMIT();
}

__global__ void __launch_bounds__(256) gemm_split_nt(
    const uint32_t* __restrict__ A, const uint32_t* __restrict__ B,
    const float* __restrict__ bias, float* __restrict__ C,
    int N, int K, long long sA, long long sB, long long sC, float alpha)
{
    extern __shared__ uint32_t sm[];
    const uint32_t sbase = smem_u32(sm);
    const int tid = threadIdx.x, wid = tid >> 5, lane = tid & 31;
    A += (long long)blockIdx.z * sA;
    B += (long long)blockIdx.z * sB;
    C += (long long)blockIdx.z * sC;
    const int bm = blockIdx.y * 128, bn = blockIdx.x * 128;
    const int warpM = (wid >> 2) * 64, warpN = (wid & 3) * 32;
    const int NC = K >> 5;
    const uint32_t* Ag = A + (long long)bm * K;
    const uint32_t* Bg = B + (long long)bn * K;

    // prologue: stages 0,1
    issue_stage(sbase, sbase + STAGE_BYTES, Ag, Bg, K, tid);
    issue_stage(sbase + 2 * STAGE_BYTES, sbase + 3 * STAGE_BYTES, Ag + 32, Bg + 32, K, tid);

    float acc[4][4][4];
    #pragma unroll
    for (int m = 0; m < 4; m++)
        #pragma unroll
        for (int n = 0; n < 4; n++)
            #pragma unroll
            for (int e = 0; e < 4; e++) acc[m][n][e] = 0.0f;

    const int r = lane >> 2, q = lane & 3;

    for (int c = 0; c < NC; c++) {
        if (c + 2 < NC) {
            int st = (c + 2) % 3;
            issue_stage(sbase + st * 2 * STAGE_BYTES, sbase + st * 2 * STAGE_BYTES + STAGE_BYTES,
                        Ag + (c + 2) * 32, Bg + (c + 2) * 32, K, tid);
        } else {
            CP_COMMIT();
        }
        CP_WAIT2();
        __syncthreads();

        const uint32_t abase = sbase + (c % 3) * 2 * STAGE_BYTES;
        const uint32_t bbase = abase + STAGE_BYTES;

        #pragma unroll
        for (int kk = 0; kk < 2; kk++) {
            const int byteC = kk * 64 + q * 8;
            uint32_t ahi[4][4], alo[4][4], bhi[4][2], blo[4][2];
            #pragma unroll
            for (int mt = 0; mt < 4; mt++) {
                int row = warpM + mt * 16 + r;
                uint32_t u0, u1, u2, u3, u4, u5, u6, u7;
                lds2(abase + swo(row,     byteC),      u0, u1);
                lds2(abase + swo(row + 8, byteC),      u2, u3);
                lds2(abase + swo(row,     byteC + 32), u4, u5);
                lds2(abase + swo(row + 8, byteC + 32), u6, u7);
                ahi[mt][0] = __byte_perm(u0, u1, 0x5410); alo[mt][0] = __byte_perm(u0, u1, 0x7632);
                ahi[mt][1] = __byte_perm(u2, u3, 0x5410); alo[mt][1] = __byte_perm(u2, u3, 0x7632);
                ahi[mt][2] = __byte_perm(u4, u5, 0x5410); alo[mt][2] = __byte_perm(u4, u5, 0x7632);
                ahi[mt][3] = __byte_perm(u6, u7, 0x5410); alo[mt][3] = __byte_perm(u6, u7, 0x7632);
            }
            #pragma unroll
            for (int nt = 0; nt < 4; nt++) {
                int row = warpN + nt * 8 + r;
                uint32_t u0, u1, u2, u3;
                lds2(bbase + swo(row, byteC),      u0, u1);
                lds2(bbase + swo(row, byteC + 32), u2, u3);
                bhi[nt][0] = __byte_perm(u0, u1, 0x5410); blo[nt][0] = __byte_perm(u0, u1, 0x7632);
                bhi[nt][1] = __byte_perm(u2, u3, 0x5410); blo[nt][1] = __byte_perm(u2, u3, 0x7632);
            }
            // pass 1: hi*hi
            #pragma unroll
            for (int mt = 0; mt < 4; mt++)
                #pragma unroll
                for (int nt = 0; nt < 4; nt++)
                    mma16816(acc[mt][nt][0], acc[mt][nt][1], acc[mt][nt][2], acc[mt][nt][3],
                             ahi[mt][0], ahi[mt][1], ahi[mt][2], ahi[mt][3], bhi[nt][0], bhi[nt][1]);
            // pass 2: hi*lo
            #pragma unroll
            for (int mt = 0; mt < 4; mt++)
                #pragma unroll
                for (int nt = 0; nt < 4; nt++)
                    mma16816(acc[mt][nt][0], acc[mt][nt][1], acc[mt][nt][2], acc[mt][nt][3],
                             ahi[mt][0], ahi[mt][1], ahi[mt][2], ahi[mt][3], blo[nt][0], blo[nt][1]);
            // pass 3: lo*hi
            #pragma unroll
            for (int mt = 0; mt < 4; mt++)
                #pragma unroll
                for (int nt = 0; nt < 4; nt++)
                    mma16816(acc[mt][nt][0], acc[mt][nt][1], acc[mt][nt][2], acc[mt][nt][3],
                             alo[mt][0], alo[mt][1], alo[mt][2], alo[mt][3], bhi[nt][0], bhi[nt][1]);
        }
        __syncthreads();
    }

    // epilogue
    #pragma unroll
    for (int mt = 0; mt < 4; mt++) {
        #pragma unroll
        for (int nt = 0; nt < 4; nt++) {
            int row = bm + warpM + mt * 16 + r;
            int col = bn + warpN + nt * 8 + q * 2;
            float b0 = 0.0f, b1 = 0.0f;
            if (bias != nullptr) { b0 = bias[col]; b1 = bias[col + 1]; }
            float2 o0 = make_float2(acc[mt][nt][0] * alpha + b0, acc[mt][nt][1] * alpha + b1);
            float2 o1 = make_float2(acc[mt][nt][2] * alpha + b0, acc[mt][nt][3] * alpha + b1);
            *(float2*)(C + (long long)row * N + col)       = o0;
            *(float2*)(C + (long long)(row + 8) * N + col) = o1;
        }
    }
}

// ---------------- fp32 -> split conversion (vectorized) ----------------
__global__ void __launch_bounds__(256) split_kernel(const float4* __restrict__ in,
                                                    uint4* __restrict__ out, int n4)
{
    int i = blockIdx.x * 256 + threadIdx.x;
    if (i >= n4) return;
    float4 v = in[i];
    uint4 o;
    o.x = split_pack(v.x); o.y = split_pack(v.y);
    o.z = split_pack(v.z); o.w = split_pack(v.w);
    out[i] = o;
}

// ---------------- RoPE on Q and K, fp32 in / split u32 out (in place) ----------------
__global__ void __launch_bounds__(256) rope_split_kernel(float* __restrict__ Q, float* __restrict__ K)
{
    int idx = blockIdx.x * 256 + threadIdx.x;    // pair index over all rows
    int i   = idx & 511;
    int row = idx >> 9;
    int s   = row & (S_LEN - 1);

    float inv_freq = powf(10000.0f, -(float)(2 * i) * (1.0f / (float)D_DIM));
    float ang = (float)s * inv_freq;
    float sn, cs;
    sincosf(ang, &sn, &cs);

    long long off = (long long)row * D_DIM + 2 * i;
    uint32_t* Qs = (uint32_t*)Q;
    uint32_t* Ks = (uint32_t*)K;
    float q0 = Q[off], q1 = Q[off + 1];
    Qs[off]     = split_pack(q0 * cs - q1 * sn);
    Qs[off + 1] = split_pack(q0 * sn + q1 * cs);
    float k0 = K[off], k1 = K[off + 1];
    Ks[off]     = split_pack(k0 * cs - k1 * sn);
    Ks[off + 1] = split_pack(k0 * sn + k1 * cs);
}

// ---------------- batched transpose + split: Vt[b][d][s] = split(V[b][s][d]) ----------------
__global__ void __launch_bounds__(256) transpose_split_kernel(const float* __restrict__ V,
                                                              uint32_t* __restrict__ Vt)
{
    __shared__ float tile[32][33];
    const float* Vb = V + (size_t)blockIdx.z * S_LEN * D_DIM;
    uint32_t* Vtb = Vt + (size_t)blockIdx.z * S_LEN * D_DIM;
    int d0 = blockIdx.x * 32, s0 = blockIdx.y * 32;
    #pragma unroll
    for (int i = 0; i < 32; i += 8)
        tile[threadIdx.y + i][threadIdx.x] = Vb[(size_t)(s0 + threadIdx.y + i) * D_DIM + d0 + threadIdx.x];
    __syncthreads();
    #pragma unroll
    for (int i = 0; i < 32; i += 8)
        Vtb[(size_t)(d0 + threadIdx.y + i) * S_LEN + s0 + threadIdx.x] =
            split_pack(tile[threadIdx.x][threadIdx.y + i]);
}

// ---------------- row softmax over S_LEN, fp32 in / split u32 out (in place) ----------------
__global__ void __launch_bounds__(256) softmax_split_kernel(float* __restrict__ P)
{
    float* row = P + (long long)blockIdx.x * S_LEN;
    uint32_t* rowo = (uint32_t*)row;
    const int tid = threadIdx.x;
    __shared__ float red[8];

    float v[8];
    float m = -1e30f;
    #pragma unroll
    for (int i = 0; i < 8; i++) {
        v[i] = row[tid + i * 256];
        m = fmaxf(m, v[i]);
    }
    #pragma unroll
    for (int o = 16; o > 0; o >>= 1) m = fmaxf(m, __shfl_xor_sync(0xFFFFFFFFu, m, o));
    if ((tid & 31) == 0) red[tid >> 5] = m;
    __syncthreads();
    m = red[0];
    #pragma unroll
    for (int i = 1; i < 8; i++) m = fmaxf(m, red[i]);
    __syncthreads();

    float sum = 0.0f;
    #pragma unroll
    for (int i = 0; i < 8; i++) {
        v[i] = expf(v[i] - m);
        sum += v[i];
    }
    #pragma unroll
    for (int o = 16; o > 0; o >>= 1) sum += __shfl_xor_sync(0xFFFFFFFFu, sum, o);
    if ((tid & 31) == 0) red[tid >> 5] = sum;
    __syncthreads();
    sum = 0.0f;
    #pragma unroll
    for (int i = 0; i < 8; i++) sum += red[i];

    float inv = 1.0f / sum;
    #pragma unroll
    for (int i = 0; i < 8; i++) rowo[tid + i * 256] = split_pack(v[i] * inv);
}

// ---------------- launch ----------------
extern "C" void kernel_launch(void* const* d_in, const int* in_sizes, int n_in,
                              void* d_out, int out_size)
{
    const float* x  = (const float*)d_in[0];
    const float* wq = (const float*)d_in[1];
    const float* bq = (const float*)d_in[2];
    const float* wk = (const float*)d_in[3];
    const float* bk = (const float*)d_in[4];
    const float* wv = (const float*)d_in[5];
    const float* bv = (const float*)d_in[6];
    float* out = (float*)d_out;

    uint32_t *Xs, *Ws, *Vt;
    float *Q, *K, *V, *Sc;
    cudaGetSymbolAddress((void**)&Xs, g_Xs);
    cudaGetSymbolAddress((void**)&Ws, g_Ws);
    cudaGetSymbolAddress((void**)&Q,  g_Q);
    cudaGetSymbolAddress((void**)&K,  g_K);
    cudaGetSymbolAddress((void**)&V,  g_V);
    cudaGetSymbolAddress((void**)&Vt, g_Vt);
    cudaGetSymbolAddress((void**)&Sc, g_S);

    cudaFuncSetAttribute(gemm_split_nt, cudaFuncAttributeMaxDynamicSharedMemorySize, SMEM_GEMM_BYTES);

    const int WN = D_DIM * D_DIM;  // 1M elems per weight

    // 0) split conversions
    split_kernel<<<(M_ROWS * D_DIM / 4 + 255) / 256, 256>>>((const float4*)x, (uint4*)Xs, M_ROWS * D_DIM / 4);
    split_kernel<<<(WN / 4 + 255) / 256, 256>>>((const float4*)wq, (uint4*)(Ws + 0 * (size_t)WN), WN / 4);
    split_kernel<<<(WN / 4 + 255) / 256, 256>>>((const float4*)wk, (uint4*)(Ws + 1 * (size_t)WN), WN / 4);
    split_kernel<<<(WN / 4 + 255) / 256, 256>>>((const float4*)wv, (uint4*)(Ws + 2 * (size_t)WN), WN / 4);

    // 1) QKV projections (M=8192, N=1024, K=1024)
    dim3 gP(D_DIM / 128, M_ROWS / 128, 1);
    gemm_split_nt<<<gP, 256, SMEM_GEMM_BYTES>>>(Xs, Ws + 0 * (size_t)WN, bq, Q, D_DIM, D_DIM, 0, 0, 0, 1.0f);
    gemm_split_nt<<<gP, 256, SMEM_GEMM_BYTES>>>(Xs, Ws + 1 * (size_t)WN, bk, K, D_DIM, D_DIM, 0, 0, 0, 1.0f);
    gemm_split_nt<<<gP, 256, SMEM_GEMM_BYTES>>>(Xs, Ws + 2 * (size_t)WN, bv, V, D_DIM, D_DIM, 0, 0, 0, 1.0f);

    // 2) RoPE + split (in place over Q,K)
    rope_split_kernel<<<(M_ROWS * (D_DIM / 2)) / 256, 256>>>(Q, K);

    // 2b) V transpose + split
    transpose_split_kernel<<<dim3(D_DIM / 32, S_LEN / 32, B_SZ), dim3(32, 8)>>>(V, Vt);

    // 3) scores = Q @ K^T / 32, batched (M=2048, N=2048, K=1024)
    dim3 gS(S_LEN / 128, S_LEN / 128, B_SZ);
    gemm_split_nt<<<gS, 256, SMEM_GEMM_BYTES>>>((const uint32_t*)Q, (const uint32_t*)K, nullptr, Sc,
                                                S_LEN, D_DIM,
                                                (long long)S_LEN * D_DIM, (long long)S_LEN * D_DIM,
                                                (long long)S_LEN * S_LEN, 0.03125f);

    // 4) softmax + split (in place)
    softmax_split_kernel<<<M_ROWS, 256>>>(Sc);

    // 5) out = P @ Vt^T, batched (M=2048, N=1024, K=2048)
    dim3 gO(D_DIM / 128, S_LEN / 128, B_SZ);
    gemm_split_nt<<<gO, 256, SMEM_GEMM_BYTES>>>((const uint32_t*)Sc, Vt, nullptr, out,
                                                D_DIM, S_LEN,
                                                (long long)S_LEN * S_LEN, (long long)S_LEN * D_DIM,
                                                (long long)S_LEN * D_DIM, 1.0f);
}

// round 4
// speedup vs baseline: 5.2941x; 1.2695x over previous
#include <cuda_runtime.h>
#include <cuda_bf16.h>
#include <math.h>
#include <stdint.h>

#define B_SZ  4
#define S_LEN 2048
#define D_DIM 1024
#define M_ROWS (B_SZ * S_LEN)   // 8192

// ---------------- scratch (allocation-free: __device__ globals) ----------------
__device__ __nv_bfloat16 g_Xhi[(size_t)M_ROWS * D_DIM];
__device__ __nv_bfloat16 g_Xlo[(size_t)M_ROWS * D_DIM];
__device__ __nv_bfloat16 g_Whi[(size_t)3 * D_DIM * D_DIM];
__device__ __nv_bfloat16 g_Wlo[(size_t)3 * D_DIM * D_DIM];
__device__ float         g_Q  [(size_t)M_ROWS * D_DIM];
__device__ float         g_K  [(size_t)M_ROWS * D_DIM];
__device__ float         g_V  [(size_t)M_ROWS * D_DIM];
__device__ __nv_bfloat16 g_Qhi[(size_t)M_ROWS * D_DIM];
__device__ __nv_bfloat16 g_Qlo[(size_t)M_ROWS * D_DIM];
__device__ __nv_bfloat16 g_Khi[(size_t)M_ROWS * D_DIM];
__device__ __nv_bfloat16 g_Klo[(size_t)M_ROWS * D_DIM];
__device__ __nv_bfloat16 g_Vthi[(size_t)M_ROWS * D_DIM];
__device__ __nv_bfloat16 g_Vtlo[(size_t)M_ROWS * D_DIM];
__device__ float         g_S  [(size_t)B_SZ * S_LEN * S_LEN];
__device__ __nv_bfloat16 g_Phi[(size_t)B_SZ * S_LEN * S_LEN];
__device__ __nv_bfloat16 g_Plo[(size_t)B_SZ * S_LEN * S_LEN];

// ======================= helpers =======================
__device__ __forceinline__ uint32_t smem_u32(const void* p) {
    uint32_t a;
    asm("{ .reg .u64 t; cvta.to.shared.u64 t, %1; cvt.u32.u64 %0, t; }" : "=r"(a) : "l"(p));
    return a;
}
// split a pair of fp32 into packed hi-bf16x2 and lo-bf16x2
__device__ __forceinline__ void split2(float a, float b, uint32_t& h, uint32_t& l) {
    __nv_bfloat16 ah = __float2bfloat16(a), bh = __float2bfloat16(b);
    __nv_bfloat16 al = __float2bfloat16(a - __bfloat162float(ah));
    __nv_bfloat16 bl = __float2bfloat16(b - __bfloat162float(bh));
    h = (uint32_t)__bfloat16_as_ushort(ah) | ((uint32_t)__bfloat16_as_ushort(bh) << 16);
    l = (uint32_t)__bfloat16_as_ushort(al) | ((uint32_t)__bfloat16_as_ushort(bl) << 16);
}
__device__ __forceinline__ void ldsm4(uint32_t& r0, uint32_t& r1, uint32_t& r2, uint32_t& r3,
                                      uint32_t addr) {
    asm volatile("ldmatrix.sync.aligned.m8n8.x4.shared.b16 {%0,%1,%2,%3}, [%4];"
                 : "=r"(r0), "=r"(r1), "=r"(r2), "=r"(r3) : "r"(addr));
}
__device__ __forceinline__ void mma16816(float& d0, float& d1, float& d2, float& d3,
                                         uint32_t a0, uint32_t a1, uint32_t a2, uint32_t a3,
                                         uint32_t b0, uint32_t b1) {
    asm volatile(
        "mma.sync.aligned.m16n8k16.row.col.f32.bf16.bf16.f32 "
        "{%0,%1,%2,%3},{%4,%5,%6,%7},{%8,%9},{%0,%1,%2,%3};"
        : "+f"(d0), "+f"(d1), "+f"(d2), "+f"(d3)
        : "r"(a0), "r"(a1), "r"(a2), "r"(a3), "r"(b0), "r"(b1));
}
__device__ __forceinline__ void cp16(uint32_t dst, const void* src) {
    asm volatile("cp.async.cg.shared.global [%0], [%1], 16;"
                 :: "r"(dst), "l"(__cvta_generic_to_global(src)) : "memory");
}
#define CP_COMMIT() asm volatile("cp.async.commit_group;" ::: "memory")
#define CP_WAIT2()  asm volatile("cp.async.wait_group 2;" ::: "memory")

// plane tile: 128 rows x 32 bf16 (64B rows), swizzle: 16B-chunk c -> c ^ ((row>>1)&3)
__device__ __forceinline__ uint32_t swp(int row, int chunk) {
    return (uint32_t)(row * 64 + ((chunk ^ ((row >> 1) & 3)) << 4));
}

// ======================= split-plane bf16 NT GEMM (3 MMAs per product) =======================
// C = alpha * (Ahi+Alo) @ (Bhi+Blo)^T + bias  (lo*lo omitted)
// A planes [M,K], B planes [N,K] row-major bf16. CTA 128x128, BK=32, 3-stage cp.async.
#define TILE_B 8192                          // one plane tile: 128*32*2
#define STAGE_BYTES (4 * TILE_B)             // Ahi,Alo,Bhi,Blo
#define SMEM_GEMM_BYTES (3 * STAGE_BYTES)    // 98304

__device__ __forceinline__ void issue_stage(
    uint32_t base, const __nv_bfloat16* Ah, const __nv_bfloat16* Al,
    const __nv_bfloat16* Bh, const __nv_bfloat16* Bl, int K, int tid)
{
    const __nv_bfloat16* src[4] = {Ah, Al, Bh, Bl};
    #pragma unroll
    for (int t = 0; t < 4; t++) {
        #pragma unroll
        for (int p = 0; p < 2; p++) {
            int cidx = tid + p * 256;          // 0..511
            int row = cidx >> 2, c = cidx & 3;
            cp16(base + t * TILE_B + swp(row, c), src[t] + (long long)row * K + c * 8);
        }
    }
    CP_COMMIT();
}

__global__ void __launch_bounds__(256, 2) gemm_split_nt(
    const __nv_bfloat16* __restrict__ Ahi, const __nv_bfloat16* __restrict__ Alo,
    const __nv_bfloat16* __restrict__ Bhi, const __nv_bfloat16* __restrict__ Blo,
    const float* __restrict__ bias, float* __restrict__ C,
    int N, int K, long long sA, long long sB, long long sC, float alpha)
{
    extern __shared__ uint32_t sm[];
    const uint32_t sbase = smem_u32(sm);
    const int tid = threadIdx.x, wid = tid >> 5, lane = tid & 31;
    Ahi += (long long)blockIdx.z * sA; Alo += (long long)blockIdx.z * sA;
    Bhi += (long long)blockIdx.z * sB; Blo += (long long)blockIdx.z * sB;
    C   += (long long)blockIdx.z * sC;
    const int bm = blockIdx.y * 128, bn = blockIdx.x * 128;
    const int warpM = (wid >> 2) * 64, warpN = (wid & 3) * 32;
    const int NC = K >> 5;
    const __nv_bfloat16* Agh = Ahi + (long long)bm * K;
    const __nv_bfloat16* Agl = Alo + (long long)bm * K;
    const __nv_bfloat16* Bgh = Bhi + (long long)bn * K;
    const __nv_bfloat16* Bgl = Blo + (long long)bn * K;

    issue_stage(sbase,               Agh,      Agl,      Bgh,      Bgl,      K, tid);
    issue_stage(sbase + STAGE_BYTES, Agh + 32, Agl + 32, Bgh + 32, Bgl + 32, K, tid);

    float acc[4][4][4];
    #pragma unroll
    for (int m = 0; m < 4; m++)
        #pragma unroll
        for (int n = 0; n < 4; n++)
            #pragma unroll
            for (int e = 0; e < 4; e++) acc[m][n][e] = 0.0f;

    // ldmatrix lane mappings
    const int laA = lane & 15, lcA = lane >> 4;                   // A: row offset, chunk half
    const int laB = (lane & 7) + ((lane & 16) >> 1);              // B: row offset
    const int lcB = (lane >> 3) & 1;                              // B: chunk half

    for (int c = 0; c < NC; c++) {
        if (c + 2 < NC) {
            int st = (c + 2) % 3;
            issue_stage(sbase + st * STAGE_BYTES,
                        Agh + (c + 2) * 32, Agl + (c + 2) * 32,
                        Bgh + (c + 2) * 32, Bgl + (c + 2) * 32, K, tid);
        } else {
            CP_COMMIT();
        }
        CP_WAIT2();
        __syncthreads();

        const uint32_t sAh = sbase + (c % 3) * STAGE_BYTES;
        const uint32_t sAl = sAh + TILE_B;
        const uint32_t sBh = sAh + 2 * TILE_B;
        const uint32_t sBl = sAh + 3 * TILE_B;

        #pragma unroll
        for (int kk = 0; kk < 2; kk++) {
            // B fragments: 2 n16 groups -> bhi/blo[nt 0..3][2]
            uint32_t bhi[4][2], blo[4][2];
            #pragma unroll
            for (int g = 0; g < 2; g++) {
                int rB = warpN + g * 16 + laB;
                uint32_t off = swp(rB, 2 * kk + lcB);
                ldsm4(bhi[2*g][0], bhi[2*g][1], bhi[2*g+1][0], bhi[2*g+1][1], sBh + off);
                ldsm4(blo[2*g][0], blo[2*g][1], blo[2*g+1][0], blo[2*g+1][1], sBl + off);
            }
            #pragma unroll
            for (int mt = 0; mt < 4; mt++) {
                int rA = warpM + mt * 16 + laA;
                uint32_t off = swp(rA, 2 * kk + lcA);
                uint32_t ah0, ah1, ah2, ah3, al0, al1, al2, al3;
                ldsm4(ah0, ah1, ah2, ah3, sAh + off);
                ldsm4(al0, al1, al2, al3, sAl + off);
                #pragma unroll
                for (int nt = 0; nt < 4; nt++)
                    mma16816(acc[mt][nt][0], acc[mt][nt][1], acc[mt][nt][2], acc[mt][nt][3],
                             ah0, ah1, ah2, ah3, bhi[nt][0], bhi[nt][1]);
                #pragma unroll
                for (int nt = 0; nt < 4; nt++)
                    mma16816(acc[mt][nt][0], acc[mt][nt][1], acc[mt][nt][2], acc[mt][nt][3],
                             ah0, ah1, ah2, ah3, blo[nt][0], blo[nt][1]);
                #pragma unroll
                for (int nt = 0; nt < 4; nt++)
                    mma16816(acc[mt][nt][0], acc[mt][nt][1], acc[mt][nt][2], acc[mt][nt][3],
                             al0, al1, al2, al3, bhi[nt][0], bhi[nt][1]);
            }
        }
        __syncthreads();
    }

    const int r = lane >> 2, q = lane & 3;
    #pragma unroll
    for (int mt = 0; mt < 4; mt++) {
        #pragma unroll
        for (int nt = 0; nt < 4; nt++) {
            int row = bm + warpM + mt * 16 + r;
            int col = bn + warpN + nt * 8 + q * 2;
            float b0 = 0.0f, b1 = 0.0f;
            if (bias != nullptr) { b0 = bias[col]; b1 = bias[col + 1]; }
            float2 o0 = make_float2(acc[mt][nt][0] * alpha + b0, acc[mt][nt][1] * alpha + b1);
            float2 o1 = make_float2(acc[mt][nt][2] * alpha + b0, acc[mt][nt][3] * alpha + b1);
            *(float2*)(C + (long long)row * N + col)       = o0;
            *(float2*)(C + (long long)(row + 8) * N + col) = o1;
        }
    }
}

// ---------------- fp32 -> hi/lo plane conversion (8 elems/thread) ----------------
__global__ void __launch_bounds__(256) split_kernel(const float* __restrict__ in,
                                                    __nv_bfloat16* __restrict__ hi,
                                                    __nv_bfloat16* __restrict__ lo, int n8)
{
    int i = blockIdx.x * 256 + threadIdx.x;
    if (i >= n8) return;
    const float4* in4 = (const float4*)in;
    float4 v0 = in4[2 * i], v1 = in4[2 * i + 1];
    uint4 h, l;
    split2(v0.x, v0.y, h.x, l.x);
    split2(v0.z, v0.w, h.y, l.y);
    split2(v1.x, v1.y, h.z, l.z);
    split2(v1.z, v1.w, h.w, l.w);
    ((uint4*)hi)[i] = h;
    ((uint4*)lo)[i] = l;
}

// ---------------- RoPE: fp32 Q,K in -> hi/lo planes out ----------------
__global__ void __launch_bounds__(256) rope_split_kernel(
    const float* __restrict__ Q, const float* __restrict__ K,
    __nv_bfloat16* __restrict__ Qhi, __nv_bfloat16* __restrict__ Qlo,
    __nv_bfloat16* __restrict__ Khi, __nv_bfloat16* __restrict__ Klo)
{
    int idx = blockIdx.x * 256 + threadIdx.x;
    int i   = idx & 511;
    int row = idx >> 9;
    int s   = row & (S_LEN - 1);

    float inv_freq = powf(10000.0f, -(float)(2 * i) * (1.0f / (float)D_DIM));
    float ang = (float)s * inv_freq;
    float sn, cs;
    sincosf(ang, &sn, &cs);

    long long off = (long long)row * D_DIM + 2 * i;
    long long u = off >> 1;
    float q0 = Q[off], q1 = Q[off + 1];
    uint32_t h, l;
    split2(q0 * cs - q1 * sn, q0 * sn + q1 * cs, h, l);
    ((uint32_t*)Qhi)[u] = h; ((uint32_t*)Qlo)[u] = l;
    float k0 = K[off], k1 = K[off + 1];
    split2(k0 * cs - k1 * sn, k0 * sn + k1 * cs, h, l);
    ((uint32_t*)Khi)[u] = h; ((uint32_t*)Klo)[u] = l;
}

// ---------------- batched transpose + split: Vt[b][d][s] = V[b][s][d] ----------------
__global__ void __launch_bounds__(256) transpose_split_kernel(
    const float* __restrict__ V, __nv_bfloat16* __restrict__ Vthi, __nv_bfloat16* __restrict__ Vtlo)
{
    __shared__ float tile[32][33];
    const float* Vb = V + (size_t)blockIdx.z * S_LEN * D_DIM;
    __nv_bfloat16* Hh = Vthi + (size_t)blockIdx.z * S_LEN * D_DIM;
    __nv_bfloat16* Hl = Vtlo + (size_t)blockIdx.z * S_LEN * D_DIM;
    int d0 = blockIdx.x * 32, s0 = blockIdx.y * 32;
    #pragma unroll
    for (int i = 0; i < 32; i += 8)
        tile[threadIdx.y + i][threadIdx.x] = Vb[(size_t)(s0 + threadIdx.y + i) * D_DIM + d0 + threadIdx.x];
    __syncthreads();
    #pragma unroll
    for (int i = 0; i < 32; i += 8) {
        float f = tile[threadIdx.x][threadIdx.y + i];
        __nv_bfloat16 h = __float2bfloat16(f);
        __nv_bfloat16 l = __float2bfloat16(f - __bfloat162float(h));
        size_t o = (size_t)(d0 + threadIdx.y + i) * S_LEN + s0 + threadIdx.x;
        Hh[o] = h; Hl[o] = l;
    }
}

// ---------------- row softmax over S_LEN, fp32 in -> hi/lo planes out ----------------
__global__ void __launch_bounds__(256) softmax_split_kernel(
    const float* __restrict__ P, __nv_bfloat16* __restrict__ Phi, __nv_bfloat16* __restrict__ Plo)
{
    const float* row = P + (long long)blockIdx.x * S_LEN;
    __nv_bfloat16* rh = Phi + (long long)blockIdx.x * S_LEN;
    __nv_bfloat16* rl = Plo + (long long)blockIdx.x * S_LEN;
    const int tid = threadIdx.x;
    __shared__ float red[8];

    float v[8];
    float m = -1e30f;
    #pragma unroll
    for (int i = 0; i < 8; i++) {
        v[i] = row[tid + i * 256];
        m = fmaxf(m, v[i]);
    }
    #pragma unroll
    for (int o = 16; o > 0; o >>= 1) m = fmaxf(m, __shfl_xor_sync(0xFFFFFFFFu, m, o));
    if ((tid & 31) == 0) red[tid >> 5] = m;
    __syncthreads();
    m = red[0];
    #pragma unroll
    for (int i = 1; i < 8; i++) m = fmaxf(m, red[i]);
    __syncthreads();

    float sum = 0.0f;
    #pragma unroll
    for (int i = 0; i < 8; i++) {
        v[i] = expf(v[i] - m);
        sum += v[i];
    }
    #pragma unroll
    for (int o = 16; o > 0; o >>= 1) sum += __shfl_xor_sync(0xFFFFFFFFu, sum, o);
    if ((tid & 31) == 0) red[tid >> 5] = sum;
    __syncthreads();
    sum = 0.0f;
    #pragma unroll
    for (int i = 0; i < 8; i++) sum += red[i];

    float inv = 1.0f / sum;
    #pragma unroll
    for (int i = 0; i < 8; i++) {
        float f = v[i] * inv;
        __nv_bfloat16 h = __float2bfloat16(f);
        __nv_bfloat16 l = __float2bfloat16(f - __bfloat162float(h));
        rh[tid + i * 256] = h;
        rl[tid + i * 256] = l;
    }
}

// ---------------- launch ----------------
extern "C" void kernel_launch(void* const* d_in, const int* in_sizes, int n_in,
                              void* d_out, int out_size)
{
    const float* x  = (const float*)d_in[0];
    const float* wq = (const float*)d_in[1];
    const float* bq = (const float*)d_in[2];
    const float* wk = (const float*)d_in[3];
    const float* bk = (const float*)d_in[4];
    const float* wv = (const float*)d_in[5];
    const float* bv = (const float*)d_in[6];
    float* out = (float*)d_out;

    __nv_bfloat16 *Xh, *Xl, *Wh, *Wl, *Qh, *Ql, *Kh, *Kl, *Vth, *Vtl, *Ph, *Pl;
    float *Q, *K, *V, *Sc;
    cudaGetSymbolAddress((void**)&Xh, g_Xhi);  cudaGetSymbolAddress((void**)&Xl, g_Xlo);
    cudaGetSymbolAddress((void**)&Wh, g_Whi);  cudaGetSymbolAddress((void**)&Wl, g_Wlo);
    cudaGetSymbolAddress((void**)&Q,  g_Q);    cudaGetSymbolAddress((void**)&K,  g_K);
    cudaGetSymbolAddress((void**)&V,  g_V);
    cudaGetSymbolAddress((void**)&Qh, g_Qhi);  cudaGetSymbolAddress((void**)&Ql, g_Qlo);
    cudaGetSymbolAddress((void**)&Kh, g_Khi);  cudaGetSymbolAddress((void**)&Kl, g_Klo);
    cudaGetSymbolAddress((void**)&Vth, g_Vthi); cudaGetSymbolAddress((void**)&Vtl, g_Vtlo);
    cudaGetSymbolAddress((void**)&Sc, g_S);
    cudaGetSymbolAddress((void**)&Ph, g_Phi);  cudaGetSymbolAddress((void**)&Pl, g_Plo);

    cudaFuncSetAttribute(gemm_split_nt, cudaFuncAttributeMaxDynamicSharedMemorySize, SMEM_GEMM_BYTES);

    const size_t WN = (size_t)D_DIM * D_DIM;

    // 0) split conversions
    split_kernel<<<(M_ROWS * D_DIM / 8 + 255) / 256, 256>>>(x, Xh, Xl, M_ROWS * D_DIM / 8);
    split_kernel<<<(WN / 8 + 255) / 256, 256>>>(wq, Wh + 0 * WN, Wl + 0 * WN, WN / 8);
    split_kernel<<<(WN / 8 + 255) / 256, 256>>>(wk, Wh + 1 * WN, Wl + 1 * WN, WN / 8);
    split_kernel<<<(WN / 8 + 255) / 256, 256>>>(wv, Wh + 2 * WN, Wl + 2 * WN, WN / 8);

    // 1) QKV projections (M=8192, N=1024, K=1024)
    dim3 gP(D_DIM / 128, M_ROWS / 128, 1);
    gemm_split_nt<<<gP, 256, SMEM_GEMM_BYTES>>>(Xh, Xl, Wh + 0 * WN, Wl + 0 * WN, bq, Q, D_DIM, D_DIM, 0, 0, 0, 1.0f);
    gemm_split_nt<<<gP, 256, SMEM_GEMM_BYTES>>>(Xh, Xl, Wh + 1 * WN, Wl + 1 * WN, bk, K, D_DIM, D_DIM, 0, 0, 0, 1.0f);
    gemm_split_nt<<<gP, 256, SMEM_GEMM_BYTES>>>(Xh, Xl, Wh + 2 * WN, Wl + 2 * WN, bv, V, D_DIM, D_DIM, 0, 0, 0, 1.0f);

    // 2) RoPE + split
    rope_split_kernel<<<(M_ROWS * (D_DIM / 2)) / 256, 256>>>(Q, K, Qh, Ql, Kh, Kl);

    // 2b) V transpose + split
    transpose_split_kernel<<<dim3(D_DIM / 32, S_LEN / 32, B_SZ), dim3(32, 8)>>>(V, Vth, Vtl);

    // 3) scores = Q @ K^T / 32, batched (M=2048, N=2048, K=1024)
    dim3 gS(S_LEN / 128, S_LEN / 128, B_SZ);
    gemm_split_nt<<<gS, 256, SMEM_GEMM_BYTES>>>(Qh, Ql, Kh, Kl, nullptr, Sc, S_LEN, D_DIM,
                                                (long long)S_LEN * D_DIM, (long long)S_LEN * D_DIM,
                                                (long long)S_LEN * S_LEN, 0.03125f);

    // 4) softmax + split
    softmax_split_kernel<<<M_ROWS, 256>>>(Sc, Ph, Pl);

    // 5) out = P @ Vt^T, batched (M=2048, N=1024, K=2048)
    dim3 gO(D_DIM / 128, S_LEN / 128, B_SZ);
    gemm_split_nt<<<gO, 256, SMEM_GEMM_BYTES>>>(Ph, Pl, Vth, Vtl, nullptr, out, D_DIM, S_LEN,
                                                (long long)S_LEN * S_LEN, (long long)S_LEN * D_DIM,
                                                (long long)S_LEN * D_DIM, 1.0f);
}

// round 6
// speedup vs baseline: 5.9287x; 1.1199x over previous
#include <cuda_runtime.h>
#include <cuda_bf16.h>
#include <math.h>
#include <stdint.h>

#define B_SZ  4
#define S_LEN 2048
#define D_DIM 1024
#define M_ROWS (B_SZ * S_LEN)   // 8192

typedef __nv_bfloat16 bf16;

// ---------------- scratch (allocation-free: __device__ globals) ----------------
__device__ bf16  g_Xhi[(size_t)M_ROWS * D_DIM];
__device__ bf16  g_Xlo[(size_t)M_ROWS * D_DIM];
__device__ bf16  g_Whi[(size_t)3 * D_DIM * D_DIM];   // [3072][1024] = wq|wk|wv rows
__device__ bf16  g_Wlo[(size_t)3 * D_DIM * D_DIM];
__device__ bf16  g_Qhi[(size_t)M_ROWS * D_DIM];
__device__ bf16  g_Qlo[(size_t)M_ROWS * D_DIM];
__device__ bf16  g_Khi[(size_t)M_ROWS * D_DIM];
__device__ bf16  g_Klo[(size_t)M_ROWS * D_DIM];
__device__ bf16  g_Vhi[(size_t)M_ROWS * D_DIM];      // row-major [b*S+s][d]
__device__ bf16  g_Vlo[(size_t)M_ROWS * D_DIM];
__device__ float g_S  [(size_t)B_SZ * S_LEN * S_LEN];
__device__ bf16  g_Phi[(size_t)B_SZ * S_LEN * S_LEN];
__device__ bf16  g_Plo[(size_t)B_SZ * S_LEN * S_LEN];

// ======================= helpers =======================
__device__ __forceinline__ uint32_t smem_u32(const void* p) {
    uint32_t a;
    asm("{ .reg .u64 t; cvta.to.shared.u64 t, %1; cvt.u32.u64 %0, t; }" : "=r"(a) : "l"(p));
    return a;
}
__device__ __forceinline__ void split2(float a, float b, uint32_t& h, uint32_t& l) {
    bf16 ah = __float2bfloat16(a), bh = __float2bfloat16(b);
    bf16 al = __float2bfloat16(a - __bfloat162float(ah));
    bf16 bl = __float2bfloat16(b - __bfloat162float(bh));
    h = (uint32_t)__bfloat16_as_ushort(ah) | ((uint32_t)__bfloat16_as_ushort(bh) << 16);
    l = (uint32_t)__bfloat16_as_ushort(al) | ((uint32_t)__bfloat16_as_ushort(bl) << 16);
}
__device__ __forceinline__ void ldsm4(uint32_t& r0, uint32_t& r1, uint32_t& r2, uint32_t& r3,
                                      uint32_t addr) {
    asm volatile("ldmatrix.sync.aligned.m8n8.x4.shared.b16 {%0,%1,%2,%3}, [%4];"
                 : "=r"(r0), "=r"(r1), "=r"(r2), "=r"(r3) : "r"(addr));
}
__device__ __forceinline__ void ldsm4t(uint32_t& r0, uint32_t& r1, uint32_t& r2, uint32_t& r3,
                                       uint32_t addr) {
    asm volatile("ldmatrix.sync.aligned.m8n8.x4.trans.shared.b16 {%0,%1,%2,%3}, [%4];"
                 : "=r"(r0), "=r"(r1), "=r"(r2), "=r"(r3) : "r"(addr));
}
__device__ __forceinline__ void mma16816(float& d0, float& d1, float& d2, float& d3,
                                         uint32_t a0, uint32_t a1, uint32_t a2, uint32_t a3,
                                         uint32_t b0, uint32_t b1) {
    asm volatile(
        "mma.sync.aligned.m16n8k16.row.col.f32.bf16.bf16.f32 "
        "{%0,%1,%2,%3},{%4,%5,%6,%7},{%8,%9},{%0,%1,%2,%3};"
        : "+f"(d0), "+f"(d1), "+f"(d2), "+f"(d3)
        : "r"(a0), "r"(a1), "r"(a2), "r"(a3), "r"(b0), "r"(b1));
}
__device__ __forceinline__ void cp16(uint32_t dst, const void* src) {
    asm volatile("cp.async.cg.shared.global [%0], [%1], 16;"
                 :: "r"(dst), "l"(__cvta_generic_to_global(src)) : "memory");
}
#define CP_COMMIT() asm volatile("cp.async.commit_group;" ::: "memory")
#define CP_WAIT2()  asm volatile("cp.async.wait_group 2;" ::: "memory")

// A tile (and NT B tile): [128 rows][32 bf16] = 64B rows; chunk c(0..3) ^= (row>>1)&3
__device__ __forceinline__ uint32_t swp(int row, int chunk) {
    return (uint32_t)(row * 64 + ((chunk ^ ((row >> 1) & 3)) << 4));
}
// NN B tile: [32 k-rows][128 n-cols] = 256B rows; chunk c(0..15) ^= k&7
__device__ __forceinline__ uint32_t swb(int k, int chunk) {
    return (uint32_t)(k * 256 + ((chunk ^ (k & 7)) << 4));
}

#define TILE_B 8192
#define STAGE_BYTES (4 * TILE_B)
#define SMEM_GEMM_BYTES (3 * STAGE_BYTES)    // 98304

// ======================= shared mainloop =======================
// BMODE 0: B = [N,K] row-major (NT).  BMODE 1: B = [K,N] row-major (NN, ldmatrix.trans)
template<int BMODE>
__device__ __forceinline__ void issue_stage(
    uint32_t base, const bf16* Agh, const bf16* Agl,
    const bf16* Bgh, const bf16* Bgl, int K, int ldB, int tid, int c)
{
    const bf16* Ah = Agh + (long long)c * 32;
    const bf16* Al = Agl + (long long)c * 32;
    #pragma unroll
    for (int p = 0; p < 2; p++) {
        int cidx = tid + p * 256;
        int row = cidx >> 2, ch = cidx & 3;
        cp16(base + 0 * TILE_B + swp(row, ch), Ah + (long long)row * K + ch * 8);
        cp16(base + 1 * TILE_B + swp(row, ch), Al + (long long)row * K + ch * 8);
    }
    if (BMODE == 0) {
        const bf16* Bh = Bgh + (long long)c * 32;
        const bf16* Bl = Bgl + (long long)c * 32;
        #pragma unroll
        for (int p = 0; p < 2; p++) {
            int cidx = tid + p * 256;
            int row = cidx >> 2, ch = cidx & 3;
            cp16(base + 2 * TILE_B + swp(row, ch), Bh + (long long)row * K + ch * 8);
            cp16(base + 3 * TILE_B + swp(row, ch), Bl + (long long)row * K + ch * 8);
        }
    } else {
        const bf16* Bh = Bgh + (long long)c * 32 * ldB;
        const bf16* Bl = Bgl + (long long)c * 32 * ldB;
        #pragma unroll
        for (int p = 0; p < 2; p++) {
            int cidx = tid + p * 256;
            int row = cidx >> 4, ch = cidx & 15;
            cp16(base + 2 * TILE_B + swb(row, ch), Bh + (long long)row * ldB + ch * 8);
            cp16(base + 3 * TILE_B + swb(row, ch), Bl + (long long)row * ldB + ch * 8);
        }
    }
    CP_COMMIT();
}

template<int BMODE>
__device__ __forceinline__ void gemm_mainloop(
    const bf16* Agh, const bf16* Agl, const bf16* Bgh, const bf16* Bgl,
    int K, int ldB, uint32_t sbase, int tid, float acc[4][4][4])
{
    const int wid = tid >> 5, lane = tid & 31;
    const int warpM = (wid >> 2) * 64, warpN = (wid & 3) * 32;
    const int NC = K >> 5;

    issue_stage<BMODE>(sbase,               Agh, Agl, Bgh, Bgl, K, ldB, tid, 0);
    issue_stage<BMODE>(sbase + STAGE_BYTES, Agh, Agl, Bgh, Bgl, K, ldB, tid, 1);

    // lane mappings
    const int laA = lane & 15, lcA = lane >> 4;          // A / NT-B
    const int laB = (lane & 7) + ((lane & 16) >> 1);
    const int lcB = (lane >> 3) & 1;
    const int lrT = lane & 7, gT = lane >> 3;            // NN-B trans

    for (int c = 0; c < NC; c++) {
        if (c + 2 < NC) {
            issue_stage<BMODE>(sbase + ((c + 2) % 3) * STAGE_BYTES,
                               Agh, Agl, Bgh, Bgl, K, ldB, tid, c + 2);
        } else {
            CP_COMMIT();
        }
        CP_WAIT2();
        __syncthreads();

        const uint32_t sAh = sbase + (c % 3) * STAGE_BYTES;
        const uint32_t sAl = sAh + TILE_B;
        const uint32_t sBh = sAh + 2 * TILE_B;
        const uint32_t sBl = sAh + 3 * TILE_B;

        #pragma unroll
        for (int kk = 0; kk < 2; kk++) {
            uint32_t bhi[4][2], blo[4][2];
            if (BMODE == 0) {
                #pragma unroll
                for (int g = 0; g < 2; g++) {
                    int rB = warpN + g * 16 + laB;
                    uint32_t off = swp(rB, 2 * kk + lcB);
                    ldsm4(bhi[2*g][0], bhi[2*g][1], bhi[2*g+1][0], bhi[2*g+1][1], sBh + off);
                    ldsm4(blo[2*g][0], blo[2*g][1], blo[2*g+1][0], blo[2*g+1][1], sBl + off);
                }
            } else {
                int k = kk * 16 + (gT & 1) * 8 + lrT;
                int cb = (warpN >> 3) + (gT >> 1);
                uint32_t off1 = swb(k, cb);
                uint32_t off2 = swb(k, cb + 2);
                ldsm4t(bhi[0][0], bhi[0][1], bhi[1][0], bhi[1][1], sBh + off1);
                ldsm4t(bhi[2][0], bhi[2][1], bhi[3][0], bhi[3][1], sBh + off2);
                ldsm4t(blo[0][0], blo[0][1], blo[1][0], blo[1][1], sBl + off1);
                ldsm4t(blo[2][0], blo[2][1], blo[3][0], blo[3][1], sBl + off2);
            }
            #pragma unroll
            for (int mt = 0; mt < 4; mt++) {
                int rA = warpM + mt * 16 + laA;
                uint32_t off = swp(rA, 2 * kk + lcA);
                uint32_t ah0, ah1, ah2, ah3, al0, al1, al2, al3;
                ldsm4(ah0, ah1, ah2, ah3, sAh + off);
                ldsm4(al0, al1, al2, al3, sAl + off);
                #pragma unroll
                for (int nt = 0; nt < 4; nt++)
                    mma16816(acc[mt][nt][0], acc[mt][nt][1], acc[mt][nt][2], acc[mt][nt][3],
                             ah0, ah1, ah2, ah3, bhi[nt][0], bhi[nt][1]);
                #pragma unroll
                for (int nt = 0; nt < 4; nt++)
                    mma16816(acc[mt][nt][0], acc[mt][nt][1], acc[mt][nt][2], acc[mt][nt][3],
                             ah0, ah1, ah2, ah3, blo[nt][0], blo[nt][1]);
                #pragma unroll
                for (int nt = 0; nt < 4; nt++)
                    mma16816(acc[mt][nt][0], acc[mt][nt][1], acc[mt][nt][2], acc[mt][nt][3],
                             al0, al1, al2, al3, bhi[nt][0], bhi[nt][1]);
            }
        }
        __syncthreads();
    }
}

// ======================= plain GEMM kernel (scores / PV) =======================
template<int BMODE>
__global__ void __launch_bounds__(256, 2) gemm_plain(
    const bf16* __restrict__ Ahi, const bf16* __restrict__ Alo,
    const bf16* __restrict__ Bhi, const bf16* __restrict__ Blo,
    float* __restrict__ C, int N, int K,
    long long sA, long long sB, long long sC, float alpha)
{
    extern __shared__ uint32_t sm[];
    const uint32_t sbase = smem_u32(sm);
    const int tid = threadIdx.x, wid = tid >> 5, lane = tid & 31;
    const int bm = blockIdx.y * 128, bn = blockIdx.x * 128;

    const bf16* Agh = Ahi + blockIdx.z * sA + (long long)bm * K;
    const bf16* Agl = Alo + blockIdx.z * sA + (long long)bm * K;
    const bf16 *Bgh, *Bgl;
    if (BMODE == 0) {
        Bgh = Bhi + blockIdx.z * sB + (long long)bn * K;
        Bgl = Blo + blockIdx.z * sB + (long long)bn * K;
    } else {
        Bgh = Bhi + blockIdx.z * sB + bn;
        Bgl = Blo + blockIdx.z * sB + bn;
    }

    float acc[4][4][4];
    #pragma unroll
    for (int m = 0; m < 4; m++)
        #pragma unroll
        for (int n = 0; n < 4; n++)
            #pragma unroll
            for (int e = 0; e < 4; e++) acc[m][n][e] = 0.0f;

    gemm_mainloop<BMODE>(Agh, Agl, Bgh, Bgl, K, (BMODE ? N : K), sbase, tid, acc);

    C += blockIdx.z * sC;
    const int warpM = (wid >> 2) * 64, warpN = (wid & 3) * 32;
    const int r = lane >> 2, q = lane & 3;
    #pragma unroll
    for (int mt = 0; mt < 4; mt++) {
        #pragma unroll
        for (int nt = 0; nt < 4; nt++) {
            int row = bm + warpM + mt * 16 + r;
            int col = bn + warpN + nt * 8 + q * 2;
            float2 o0 = make_float2(acc[mt][nt][0] * alpha, acc[mt][nt][1] * alpha);
            float2 o1 = make_float2(acc[mt][nt][2] * alpha, acc[mt][nt][3] * alpha);
            *(float2*)(C + (long long)row * N + col)       = o0;
            *(float2*)(C + (long long)(row + 8) * N + col) = o1;
        }
    }
}

// ======================= fused projection GEMM: QKV + bias + RoPE + split =======================
__global__ void __launch_bounds__(256, 2) gemm_proj(
    const bf16* __restrict__ Ahi, const bf16* __restrict__ Alo,
    const bf16* __restrict__ Bhi, const bf16* __restrict__ Blo,
    const float* __restrict__ bq, const float* __restrict__ bk, const float* __restrict__ bv,
    bf16* __restrict__ Qh, bf16* __restrict__ Ql,
    bf16* __restrict__ Kh, bf16* __restrict__ Kl,
    bf16* __restrict__ Vh, bf16* __restrict__ Vl)
{
    extern __shared__ uint32_t sm[];
    const uint32_t sbase = smem_u32(sm);
    const int tid = threadIdx.x, wid = tid >> 5, lane = tid & 31;
    const int bm = blockIdx.y * 128, bn = blockIdx.x * 128;
    const int K = D_DIM;

    const bf16* Agh = Ahi + (long long)bm * K;
    const bf16* Agl = Alo + (long long)bm * K;
    const bf16* Bgh = Bhi + (long long)bn * K;
    const bf16* Bgl = Blo + (long long)bn * K;

    float acc[4][4][4];
    #pragma unroll
    for (int m = 0; m < 4; m++)
        #pragma unroll
        for (int n = 0; n < 4; n++)
            #pragma unroll
            for (int e = 0; e < 4; e++) acc[m][n][e] = 0.0f;

    gemm_mainloop<0>(Agh, Agl, Bgh, Bgl, K, K, sbase, tid, acc);

    const int warpM = (wid >> 2) * 64, warpN = (wid & 3) * 32;
    const int r = lane >> 2, q = lane & 3;
    const int sel = bn >> 10;                   // uniform per CTA (bn multiple of 128)
    const float* bias = (sel == 0) ? bq : (sel == 1) ? bk : bv;
    uint32_t* Oh = (uint32_t*)((sel == 0) ? Qh : (sel == 1) ? Kh : Vh);
    uint32_t* Ol = (uint32_t*)((sel == 0) ? Ql : (sel == 1) ? Kl : Vl);

    #pragma unroll
    for (int nt = 0; nt < 4; nt++) {
        int col = bn + warpN + nt * 8 + q * 2;   // even
        int cl  = col & 1023;
        float b0 = bias[cl], b1 = bias[cl + 1];
        float invf = (sel < 2) ? powf(10000.0f, -(float)cl * (1.0f / (float)D_DIM)) : 0.0f;
        #pragma unroll
        for (int mt = 0; mt < 4; mt++) {
            #pragma unroll
            for (int rr = 0; rr < 2; rr++) {
                int row = bm + warpM + mt * 16 + r + rr * 8;
                float v0 = acc[mt][nt][rr * 2 + 0] + b0;
                float v1 = acc[mt][nt][rr * 2 + 1] + b1;
                if (sel < 2) {
                    int s = row & (S_LEN - 1);
                    float sn, cs;
                    sincosf((float)s * invf, &sn, &cs);
                    float t0 = v0 * cs - v1 * sn;
                    float t1 = v0 * sn + v1 * cs;
                    v0 = t0; v1 = t1;
                }
                uint32_t h, l;
                split2(v0, v1, h, l);
                long long off = (long long)row * (D_DIM / 2) + (cl >> 1);
                Oh[off] = h;
                Ol[off] = l;
            }
        }
    }
}

// ---------------- fp32 -> hi/lo plane conversion ----------------
__global__ void __launch_bounds__(256) split_kernel(const float* __restrict__ in,
                                                    bf16* __restrict__ hi,
                                                    bf16* __restrict__ lo, int n8)
{
    int i = blockIdx.x * 256 + threadIdx.x;
    if (i >= n8) return;
    const float4* in4 = (const float4*)in;
    float4 v0 = in4[2 * i], v1 = in4[2 * i + 1];
    uint4 h, l;
    split2(v0.x, v0.y, h.x, l.x);
    split2(v0.z, v0.w, h.y, l.y);
    split2(v1.x, v1.y, h.z, l.z);
    split2(v1.z, v1.w, h.w, l.w);
    ((uint4*)hi)[i] = h;
    ((uint4*)lo)[i] = l;
}

// ---------------- row softmax over S_LEN, fp32 in -> hi/lo planes out ----------------
__global__ void __launch_bounds__(256) softmax_split_kernel(
    const float* __restrict__ P, bf16* __restrict__ Phi, bf16* __restrict__ Plo)
{
    const float* row = P + (long long)blockIdx.x * S_LEN;
    bf16* rh = Phi + (long long)blockIdx.x * S_LEN;
    bf16* rl = Plo + (long long)blockIdx.x * S_LEN;
    const int tid = threadIdx.x;
    __shared__ float red[8];

    float v[8];
    float m = -1e30f;
    #pragma unroll
    for (int i = 0; i < 8; i++) {
        v[i] = row[tid + i * 256];
        m = fmaxf(m, v[i]);
    }
    #pragma unroll
    for (int o = 16; o > 0; o >>= 1) m = fmaxf(m, __shfl_xor_sync(0xFFFFFFFFu, m, o));
    if ((tid & 31) == 0) red[tid >> 5] = m;
    __syncthreads();
    m = red[0];
    #pragma unroll
    for (int i = 1; i < 8; i++) m = fmaxf(m, red[i]);
    __syncthreads();

    float sum = 0.0f;
    #pragma unroll
    for (int i = 0; i < 8; i++) {
        v[i] = expf(v[i] - m);
        sum += v[i];
    }
    #pragma unroll
    for (int o = 16; o > 0; o >>= 1) sum += __shfl_xor_sync(0xFFFFFFFFu, sum, o);
    if ((tid & 31) == 0) red[tid >> 5] = sum;
    __syncthreads();
    sum = 0.0f;
    #pragma unroll
    for (int i = 0; i < 8; i++) sum += red[i];

    float inv = 1.0f / sum;
    #pragma unroll
    for (int i = 0; i < 8; i++) {
        float f = v[i] * inv;
        bf16 h = __float2bfloat16(f);
        bf16 l = __float2bfloat16(f - __bfloat162float(h));
        rh[tid + i * 256] = h;
        rl[tid + i * 256] = l;
    }
}

// ---------------- launch ----------------
extern "C" void kernel_launch(void* const* d_in, const int* in_sizes, int n_in,
                              void* d_out, int out_size)
{
    const float* x  = (const float*)d_in[0];
    const float* wq = (const float*)d_in[1];
    const float* bq = (const float*)d_in[2];
    const float* wk = (const float*)d_in[3];
    const float* bk = (const float*)d_in[4];
    const float* wv = (const float*)d_in[5];
    const float* bv = (const float*)d_in[6];
    float* out = (float*)d_out;

    bf16 *Xh, *Xl, *Wh, *Wl, *Qh, *Ql, *Kh, *Kl, *Vh, *Vl, *Ph, *Pl;
    float *Sc;
    cudaGetSymbolAddress((void**)&Xh, g_Xhi);  cudaGetSymbolAddress((void**)&Xl, g_Xlo);
    cudaGetSymbolAddress((void**)&Wh, g_Whi);  cudaGetSymbolAddress((void**)&Wl, g_Wlo);
    cudaGetSymbolAddress((void**)&Qh, g_Qhi);  cudaGetSymbolAddress((void**)&Ql, g_Qlo);
    cudaGetSymbolAddress((void**)&Kh, g_Khi);  cudaGetSymbolAddress((void**)&Kl, g_Klo);
    cudaGetSymbolAddress((void**)&Vh, g_Vhi);  cudaGetSymbolAddress((void**)&Vl, g_Vlo);
    cudaGetSymbolAddress((void**)&Sc, g_S);
    cudaGetSymbolAddress((void**)&Ph, g_Phi);  cudaGetSymbolAddress((void**)&Pl, g_Plo);

    cudaFuncSetAttribute(gemm_plain<0>, cudaFuncAttributeMaxDynamicSharedMemorySize, SMEM_GEMM_BYTES);
    cudaFuncSetAttribute(gemm_plain<1>, cudaFuncAttributeMaxDynamicSharedMemorySize, SMEM_GEMM_BYTES);
    cudaFuncSetAttribute(gemm_proj,     cudaFuncAttributeMaxDynamicSharedMemorySize, SMEM_GEMM_BYTES);

    const size_t WN = (size_t)D_DIM * D_DIM;

    // 0) split conversions (x, and W concatenated as [3072][1024])
    split_kernel<<<(M_ROWS * D_DIM / 8 + 255) / 256, 256>>>(x, Xh, Xl, M_ROWS * D_DIM / 8);
    split_kernel<<<(WN / 8 + 255) / 256, 256>>>(wq, Wh + 0 * WN, Wl + 0 * WN, WN / 8);
    split_kernel<<<(WN / 8 + 255) / 256, 256>>>(wk, Wh + 1 * WN, Wl + 1 * WN, WN / 8);
    split_kernel<<<(WN / 8 + 255) / 256, 256>>>(wv, Wh + 2 * WN, Wl + 2 * WN, WN / 8);

    // 1) fused QKV projection + bias + RoPE + split (M=8192, N=3072, K=1024)
    dim3 gP(3 * D_DIM / 128, M_ROWS / 128, 1);
    gemm_proj<<<gP, 256, SMEM_GEMM_BYTES>>>(Xh, Xl, Wh, Wl, bq, bk, bv,
                                            Qh, Ql, Kh, Kl, Vh, Vl);

    // 2) scores = Q @ K^T / 32, batched (M=2048, N=2048, K=1024)
    dim3 gS(S_LEN / 128, S_LEN / 128, B_SZ);
    gemm_plain<0><<<gS, 256, SMEM_GEMM_BYTES>>>(Qh, Ql, Kh, Kl, Sc, S_LEN, D_DIM,
                                                (long long)S_LEN * D_DIM, (long long)S_LEN * D_DIM,
                                                (long long)S_LEN * S_LEN, 0.03125f);

    // 3) softmax + split
    softmax_split_kernel<<<M_ROWS, 256>>>(Sc, Ph, Pl);

    // 4) out = P @ V (V row-major [s][d], NN via ldmatrix.trans), batched
    dim3 gO(D_DIM / 128, S_LEN / 128, B_SZ);
    gemm_plain<1><<<gO, 256, SMEM_GEMM_BYTES>>>(Ph, Pl, Vh, Vl, out, D_DIM, S_LEN,
                                                (long long)S_LEN * S_LEN, (long long)S_LEN * D_DIM,
                                                (long long)S_LEN * D_DIM, 1.0f);
}